// round 1
// baseline (speedup 1.0000x reference)
#include <cuda_runtime.h>
#include <cstdint>

// Problem constants
#define S    8192      // tokens
#define E    64        // experts
#define DIM  4096      // model dim
#define CAP  128       // capacity = ceil(S/E * 1.0)
#define KSPLIT 4
#define KPER (DIM / KSPLIT)   // 1024
#define BK 32
#define BM 128
#define BN 64

// Output layout (all float32, concatenated in reference return order):
// [0]                 l_aux
// [1 .. 1+S*E*CAP)    combine_weights
// [.. + S*E*CAP)      dispatch_mask (0/1)
// [.. + E)            exp_counts
#define OFF_COMBINE 1ULL
#define ROW (E * CAP)                          // 8192 floats per token per tensor
#define OFF_MASK   (1ULL + (unsigned long long)S * ROW)
#define OFF_COUNTS (1ULL + 2ULL * (unsigned long long)S * ROW)

// ---------------- device scratch (no allocations allowed) ----------------
__device__ float g_lpart[KSPLIT * S * E];          // split-K partial logits, 8 MB
__device__ float g_colsum_part[(S / 8) * E];       // per-block gate column sums
__device__ int   g_expert[S];
__device__ float g_gate[S];
__device__ float g_noise[S];
__device__ int   g_slot[S];
__device__ int   g_counts[E];

// ---------------- helpers ----------------
__device__ __forceinline__ void fma2(unsigned long long& acc,
                                     unsigned long long a,
                                     unsigned long long b) {
    asm("fma.rn.f32x2 %0, %1, %2, %3;" : "=l"(acc) : "l"(a), "l"(b), "l"(acc));
}

// ---------------- Kernel Z: init small scratch ----------------
__global__ void init_kernel() {
    if (threadIdx.x < E) g_counts[threadIdx.x] = 0;
}

// ---------------- Kernel A: split-K GEMM, fp32 via packed f32x2 ----------------
// logits_part[ks][t][e] = sum_{k in split ks} x[t][k] * w[e][k]
__global__ void __launch_bounds__(256) gemm_kernel(const float* __restrict__ x,
                                                   const float* __restrict__ w) {
    __shared__ unsigned long long xs[16][BM + 1];  // [k-pair][token], pitch 129
    __shared__ unsigned long long ws[16][BN + 1];  // [k-pair][expert], pitch 65

    const int tid = threadIdx.x;
    const int tx = tid & 15;   // expert group: experts tx + 16*j
    const int ty = tid >> 4;   // token group:  tokens ty + 16*i
    const int tok0 = blockIdx.x * BM;
    const int ks = blockIdx.y;
    const int kbase = ks * KPER;

    unsigned long long acc[8][4];
#pragma unroll
    for (int i = 0; i < 8; ++i)
#pragma unroll
        for (int j = 0; j < 4; ++j) acc[i][j] = 0ULL;

    for (int it = 0; it < KPER / BK; ++it) {
        const int k0 = kbase + it * BK;
        // load x tile: 128 tokens x 32 k = 1024 float4
#pragma unroll
        for (int pass = 0; pass < 4; ++pass) {
            int u = tid + pass * 256;
            int t = u >> 3;
            int v = u & 7;
            const float4 f = *reinterpret_cast<const float4*>(
                &x[(size_t)(tok0 + t) * DIM + k0 + v * 4]);
            xs[v * 2][t]     = *reinterpret_cast<const unsigned long long*>(&f.x);
            xs[v * 2 + 1][t] = *reinterpret_cast<const unsigned long long*>(&f.z);
        }
        // load w tile: 64 experts x 32 k = 512 float4
#pragma unroll
        for (int pass = 0; pass < 2; ++pass) {
            int u = tid + pass * 256;
            int e = u >> 3;
            int v = u & 7;
            const float4 f = *reinterpret_cast<const float4*>(
                &w[(size_t)e * DIM + k0 + v * 4]);
            ws[v * 2][e]     = *reinterpret_cast<const unsigned long long*>(&f.x);
            ws[v * 2 + 1][e] = *reinterpret_cast<const unsigned long long*>(&f.z);
        }
        __syncthreads();

#pragma unroll
        for (int p = 0; p < 16; ++p) {
            unsigned long long xv[8], wv[4];
#pragma unroll
            for (int i = 0; i < 8; ++i) xv[i] = xs[p][ty + 16 * i];
#pragma unroll
            for (int j = 0; j < 4; ++j) wv[j] = ws[p][tx + 16 * j];
#pragma unroll
            for (int i = 0; i < 8; ++i)
#pragma unroll
                for (int j = 0; j < 4; ++j) fma2(acc[i][j], xv[i], wv[j]);
        }
        __syncthreads();
    }

#pragma unroll
    for (int i = 0; i < 8; ++i) {
        const int t = tok0 + ty + 16 * i;
#pragma unroll
        for (int j = 0; j < 4; ++j) {
            const int e = tx + 16 * j;
            float2 f = *reinterpret_cast<float2*>(&acc[i][j]);
            g_lpart[((size_t)ks * S + t) * E + e] = f.x + f.y;
        }
    }
}

// ---------------- Kernel B: reduce split-K, softmax, argmax, stats ----------------
__global__ void __launch_bounds__(256) gate_kernel(const float* __restrict__ noise) {
    __shared__ float sg[8][E];
    const int tid = threadIdx.x;
    const int w = tid >> 5;
    const int lane = tid & 31;
    const int t = blockIdx.x * 8 + w;
    const int e0 = lane, e1 = lane + 32;

    float l0 = 0.f, l1 = 0.f;
#pragma unroll
    for (int ks = 0; ks < KSPLIT; ++ks) {
        l0 += g_lpart[((size_t)ks * S + t) * E + e0];
        l1 += g_lpart[((size_t)ks * S + t) * E + e1];
    }
    // softmax over 64
    float m = fmaxf(l0, l1);
#pragma unroll
    for (int off = 16; off > 0; off >>= 1)
        m = fmaxf(m, __shfl_xor_sync(0xffffffffu, m, off));
    float p0 = expf(l0 - m), p1 = expf(l1 - m);
    float ssum = p0 + p1;
#pragma unroll
    for (int off = 16; off > 0; off >>= 1)
        ssum += __shfl_xor_sync(0xffffffffu, ssum, off);
    float g0 = p0 / ssum, g1 = p1 / ssum;

    // argmax (ties -> lowest index, matching jnp.argmax)
    float bv; int bi;
    if (l0 >= l1) { bv = l0; bi = e0; } else { bv = l1; bi = e1; }
#pragma unroll
    for (int off = 16; off > 0; off >>= 1) {
        float ov = __shfl_xor_sync(0xffffffffu, bv, off);
        int   oi = __shfl_xor_sync(0xffffffffu, bi, off);
        if (ov > bv || (ov == bv && oi < bi)) { bv = ov; bi = oi; }
    }
    float gown = (bi < 32) ? g0 : g1;
    float gbest = __shfl_sync(0xffffffffu, gown, bi & 31);

    if (lane == 0) {
        g_expert[t] = bi;
        g_gate[t]   = gbest;
        g_noise[t]  = noise[(size_t)t * E + bi];
        g_slot[t]   = -1;
        atomicAdd(&g_counts[bi], 1);
    }

    sg[w][e0] = g0;
    sg[w][e1] = g1;
    __syncthreads();
    if (tid < E) {
        float cs = 0.f;
#pragma unroll
        for (int ww = 0; ww < 8; ++ww) cs += sg[ww][tid];
        g_colsum_part[blockIdx.x * E + tid] = cs;
    }
}

// ---------------- Kernel C: per-expert capacity selection (jax top_k semantics) --
__global__ void __launch_bounds__(256) select_kernel() {
    const int e = blockIdx.x;
    __shared__ unsigned long long keys[1024];
    __shared__ int wc[8], wo[8], sh_chunk;
    __shared__ unsigned int toks[CAP];
    const int tid = threadIdx.x;
    const int w = tid >> 5;
    const int lane = tid & 31;

    int total = 0;
    for (int base = 0; base < S; base += 256) {
        const int t = base + tid;
        const bool match = (g_expert[t] == e);
        unsigned bal = __ballot_sync(0xffffffffu, match);
        const int pre = __popc(bal & ((1u << lane) - 1u));
        if (lane == 0) wc[w] = __popc(bal);
        __syncthreads();
        if (tid == 0) {
            int o = 0;
            for (int i = 0; i < 8; ++i) { wo[i] = o; o += wc[i]; }
            sh_chunk = o;
        }
        __syncthreads();
        if (match) {
            const int pos = total + wo[w] + pre;
            if (pos < 1024) {
                keys[pos] = ((unsigned long long)__float_as_uint(g_noise[t]) << 32)
                          | (unsigned)(0xFFFFFFFFu - (unsigned)t);
            }
        }
        total += sh_chunk;
    }
    __syncthreads();
    const int n = total;

    if (n <= CAP) {
        // all selected; slot = rank by token index (compaction is in-order)
        for (int j = tid; j < n; j += 256) {
            unsigned tkn = 0xFFFFFFFFu - (unsigned)(keys[j] & 0xFFFFFFFFu);
            g_slot[tkn] = j;
        }
    } else {
        // pad then descending bitonic sort on (noise, ~token) -> jax top_k order
        for (int j = tid; j < 1024; j += 256)
            if (j >= n) keys[j] = 0ULL;
        __syncthreads();
        for (int k = 2; k <= 1024; k <<= 1) {
            for (int j = k >> 1; j > 0; j >>= 1) {
                for (int i = tid; i < 1024; i += 256) {
                    int ixj = i ^ j;
                    if (ixj > i) {
                        unsigned long long a = keys[i], b = keys[ixj];
                        bool desc = ((i & k) == 0);
                        if (desc ? (a < b) : (a > b)) { keys[i] = b; keys[ixj] = a; }
                    }
                }
                __syncthreads();
            }
        }
        if (tid < CAP)
            toks[tid] = 0xFFFFFFFFu - (unsigned)(keys[tid] & 0xFFFFFFFFu);
        __syncthreads();
        // ascending bitonic over the 128 selected tokens -> slot = index rank
        for (int k = 2; k <= CAP; k <<= 1) {
            for (int j = k >> 1; j > 0; j >>= 1) {
                if (tid < CAP) {
                    int i = tid, ixj = i ^ j;
                    if (ixj > i) {
                        unsigned a = toks[i], b = toks[ixj];
                        bool asc = ((i & k) == 0);
                        if (asc ? (a > b) : (a < b)) { toks[i] = b; toks[ixj] = a; }
                    }
                }
                __syncthreads();
            }
        }
        if (tid < CAP) g_slot[toks[tid]] = tid;
    }
}

// ---------------- Kernel Z2: zero-fill output region [1, OFF_COUNTS) -----------
__global__ void zero_kernel(float* __restrict__ out) {
    const size_t nf4 = (OFF_COUNTS - 4ULL) >> 2;       // float4s starting at elem 4
    float4* p = reinterpret_cast<float4*>(out + 4);
    const size_t stride = (size_t)gridDim.x * blockDim.x;
    const float4 z = make_float4(0.f, 0.f, 0.f, 0.f);
    for (size_t i = (size_t)blockIdx.x * blockDim.x + threadIdx.x; i < nf4; i += stride)
        p[i] = z;
    if (blockIdx.x == 0 && threadIdx.x < 3) out[1 + threadIdx.x] = 0.f;
    if (blockIdx.x == 0 && threadIdx.x == 0) {
        for (size_t i = 4 + 4 * nf4; i < OFF_COUNTS; ++i) out[i] = 0.f;
    }
}

// ---------------- Kernel D: sparse scatter of combine/dispatch ----------------
__global__ void scatter_kernel(float* __restrict__ out) {
    const int t = blockIdx.x * blockDim.x + threadIdx.x;
    if (t >= S) return;
    const int s = g_slot[t];
    if (s >= 0) {
        const int e = g_expert[t];
        const size_t idx = (size_t)t * ROW + (size_t)e * CAP + s;
        out[OFF_COMBINE + idx] = g_gate[t];
        out[OFF_MASK + idx]    = 1.0f;
    }
}

// ---------------- Kernel E: l_aux + exp_counts ----------------
__global__ void scalars_kernel(float* __restrict__ out) {
    __shared__ float prod[E];
    const int e = threadIdx.x;
    if (e < E) {
        float cs = 0.f;
        for (int b = 0; b < S / 8; ++b) cs += g_colsum_part[b * E + e];
        out[OFF_COUNTS + e] = (float)g_counts[e];
        prod[e] = cs * (float)g_counts[e];
    }
    __syncthreads();
    if (e == 0) {
        float a = 0.f;
        for (int i = 0; i < E; ++i) a += prod[i];
        out[0] = a * ((float)E / ((float)S * (float)S));
    }
}

// ---------------- launch ----------------
extern "C" void kernel_launch(void* const* d_in, const int* in_sizes, int n_in,
                              void* d_out, int out_size) {
    // identify inputs by element count (robust to ordering)
    const float *x = nullptr, *wg = nullptr, *noise = nullptr;
    for (int i = 0; i < n_in; ++i) {
        if (in_sizes[i] == S * DIM)      x     = (const float*)d_in[i];
        else if (in_sizes[i] == E * DIM) wg    = (const float*)d_in[i];
        else if (in_sizes[i] == S * E)   noise = (const float*)d_in[i];
    }
    float* out = (float*)d_out;

    init_kernel<<<1, 64>>>();
    gemm_kernel<<<dim3(S / BM, KSPLIT), 256>>>(x, wg);
    gate_kernel<<<S / 8, 256>>>(noise);
    select_kernel<<<E, 256>>>();
    zero_kernel<<<2048, 256>>>(out);
    scatter_kernel<<<(S + 255) / 256, 256>>>(out);
    scalars_kernel<<<1, 64>>>(out);
}

// round 2
// speedup vs baseline: 1.2217x; 1.2217x over previous
#include <cuda_runtime.h>
#include <cstdint>

// Problem constants
#define S    8192      // tokens
#define E    64        // experts
#define DIM  4096      // model dim
#define CAP  128       // capacity
#define KSPLIT 4
#define KPER (DIM / KSPLIT)   // 1024
#define BK 32
#define BM 128
#define BN 64
#define GEMM_BLOCKS ((S / BM) * KSPLIT)   // 256
#define ZERO_BLOCKS 1792
#define LISTCAP 8192

// Output layout (float32):
// [0] l_aux | [1 .. 1+S*E*CAP) combine | [..) dispatch mask | [..+E) exp_counts
#define OFF_COMBINE 1ULL
#define ROW (E * CAP)
#define OFF_MASK   (1ULL + (unsigned long long)S * ROW)
#define OFF_COUNTS (1ULL + 2ULL * (unsigned long long)S * ROW)

// ---------------- device scratch ----------------
__device__ float g_lpart[KSPLIT * S * E];            // split-K partial logits
__device__ float g_colsum_part[(S / 8) * E];         // gate column partial sums
__device__ int   g_expert[S];
__device__ float g_gate[S];
__device__ int   g_slot[S];
__device__ int   g_cnt[E];                           // per-expert member count
__device__ unsigned long long g_keys[E * LISTCAP];   // per-expert (noise,~tok) keys

__device__ __forceinline__ void fma2(unsigned long long& acc,
                                     unsigned long long a,
                                     unsigned long long b) {
    asm("fma.rn.f32x2 %0, %1, %2, %3;" : "=l"(acc) : "l"(a), "l"(b), "l"(acc));
}

// ---------------- Kernel A: fused split-K GEMM + output zero-fill ----------------
__global__ void __launch_bounds__(256) fused_gemm_zero_kernel(
        const float* __restrict__ x, const float* __restrict__ w,
        float* __restrict__ out) {
    const int tid = threadIdx.x;

    if (blockIdx.x >= GEMM_BLOCKS) {
        // ---------- zero-fill branch (DRAM-bound, hides under GEMM) ----------
        const int zid = blockIdx.x - GEMM_BLOCKS;
        if (zid == 0 && tid < E) g_cnt[tid] = 0;
        const size_t nf4 = (OFF_COUNTS - 4ULL) >> 2;
        float4* p = reinterpret_cast<float4*>(out + 4);
        const size_t stride = (size_t)ZERO_BLOCKS * 256;
        const float4 z = make_float4(0.f, 0.f, 0.f, 0.f);
        for (size_t i = (size_t)zid * 256 + tid; i < nf4; i += stride) p[i] = z;
        if (zid == 0 && tid < 3) out[1 + tid] = 0.f;
        if (zid == 0 && tid == 0)
            for (size_t i = 4 + 4 * nf4; i < OFF_COUNTS; ++i) out[i] = 0.f;
        return;
    }

    // ---------- GEMM branch: fp32 via packed f32x2 ----------
    __shared__ unsigned long long xs[16][BM + 1];
    __shared__ unsigned long long ws[16][BN + 1];

    const int tx = tid & 15;
    const int ty = tid >> 4;
    const int tok0 = (blockIdx.x & (S / BM - 1)) * BM;
    const int ks = blockIdx.x / (S / BM);
    const int kbase = ks * KPER;

    unsigned long long acc[8][4];
#pragma unroll
    for (int i = 0; i < 8; ++i)
#pragma unroll
        for (int j = 0; j < 4; ++j) acc[i][j] = 0ULL;

    for (int it = 0; it < KPER / BK; ++it) {
        const int k0 = kbase + it * BK;
#pragma unroll
        for (int pass = 0; pass < 4; ++pass) {
            int u = tid + pass * 256;
            int t = u >> 3;
            int v = u & 7;
            const float4 f = *reinterpret_cast<const float4*>(
                &x[(size_t)(tok0 + t) * DIM + k0 + v * 4]);
            xs[v * 2][t]     = *reinterpret_cast<const unsigned long long*>(&f.x);
            xs[v * 2 + 1][t] = *reinterpret_cast<const unsigned long long*>(&f.z);
        }
#pragma unroll
        for (int pass = 0; pass < 2; ++pass) {
            int u = tid + pass * 256;
            int e = u >> 3;
            int v = u & 7;
            const float4 f = *reinterpret_cast<const float4*>(
                &w[(size_t)e * DIM + k0 + v * 4]);
            ws[v * 2][e]     = *reinterpret_cast<const unsigned long long*>(&f.x);
            ws[v * 2 + 1][e] = *reinterpret_cast<const unsigned long long*>(&f.z);
        }
        __syncthreads();

#pragma unroll
        for (int p = 0; p < 16; ++p) {
            unsigned long long xv[8], wv[4];
#pragma unroll
            for (int i = 0; i < 8; ++i) xv[i] = xs[p][ty + 16 * i];
#pragma unroll
            for (int j = 0; j < 4; ++j) wv[j] = ws[p][tx + 16 * j];
#pragma unroll
            for (int i = 0; i < 8; ++i)
#pragma unroll
                for (int j = 0; j < 4; ++j) fma2(acc[i][j], xv[i], wv[j]);
        }
        __syncthreads();
    }

#pragma unroll
    for (int i = 0; i < 8; ++i) {
        const int t = tok0 + ty + 16 * i;
#pragma unroll
        for (int j = 0; j < 4; ++j) {
            const int e = tx + 16 * j;
            float2 f = *reinterpret_cast<float2*>(&acc[i][j]);
            g_lpart[((size_t)ks * S + t) * E + e] = f.x + f.y;
        }
    }
}

// ---------------- Kernel B: reduce split-K, softmax, argmax, key append --------
__global__ void __launch_bounds__(256) gate_kernel(const float* __restrict__ noise) {
    __shared__ float sg[8][E];
    const int tid = threadIdx.x;
    const int w = tid >> 5;
    const int lane = tid & 31;
    const int t = blockIdx.x * 8 + w;
    const int e0 = lane, e1 = lane + 32;

    float l0 = 0.f, l1 = 0.f;
#pragma unroll
    for (int ks = 0; ks < KSPLIT; ++ks) {
        l0 += g_lpart[((size_t)ks * S + t) * E + e0];
        l1 += g_lpart[((size_t)ks * S + t) * E + e1];
    }
    float m = fmaxf(l0, l1);
#pragma unroll
    for (int off = 16; off > 0; off >>= 1)
        m = fmaxf(m, __shfl_xor_sync(0xffffffffu, m, off));
    float p0 = expf(l0 - m), p1 = expf(l1 - m);
    float ssum = p0 + p1;
#pragma unroll
    for (int off = 16; off > 0; off >>= 1)
        ssum += __shfl_xor_sync(0xffffffffu, ssum, off);
    float g0 = p0 / ssum, g1 = p1 / ssum;

    // argmax, ties -> lowest index
    float bv; int bi;
    if (l0 >= l1) { bv = l0; bi = e0; } else { bv = l1; bi = e1; }
#pragma unroll
    for (int off = 16; off > 0; off >>= 1) {
        float ov = __shfl_xor_sync(0xffffffffu, bv, off);
        int   oi = __shfl_xor_sync(0xffffffffu, bi, off);
        if (ov > bv || (ov == bv && oi < bi)) { bv = ov; bi = oi; }
    }
    float gown = (bi < 32) ? g0 : g1;
    float gbest = __shfl_sync(0xffffffffu, gown, bi & 31);

    if (lane == 0) {
        g_expert[t] = bi;
        g_gate[t]   = gbest;
        g_slot[t]   = -1;
        const float nz = noise[(size_t)t * E + bi];
        const int pos = atomicAdd(&g_cnt[bi], 1);
        g_keys[(size_t)bi * LISTCAP + pos] =
            ((unsigned long long)__float_as_uint(nz) << 32)
            | (unsigned)(0xFFFFFFFFu - (unsigned)t);
    }

    sg[w][e0] = g0;
    sg[w][e1] = g1;
    __syncthreads();
    if (tid < E) {
        float cs = 0.f;
#pragma unroll
        for (int ww = 0; ww < 8; ++ww) cs += sg[ww][tid];
        g_colsum_part[blockIdx.x * E + tid] = cs;
    }
}

// ---------------- Kernel C: per-expert top-CAP selection + slot ranks -----------
__global__ void __launch_bounds__(256) select_kernel() {
    const int e = blockIdx.x;
    const int tid = threadIdx.x;
    __shared__ unsigned long long keys[2048];
    __shared__ unsigned toks[CAP];
    __shared__ unsigned long long red[256];

    const int n = g_cnt[e];
    int sel;

    if (n <= 2048) {
        int m = 1;
        while (m < n) m <<= 1;
        for (int j = tid; j < m; j += 256)
            keys[j] = (j < n) ? g_keys[(size_t)e * LISTCAP + j] : 0ULL;
        __syncthreads();
        // bitonic sort, descending on (noise, ~token)
        for (int k = 2; k <= m; k <<= 1) {
            for (int j = k >> 1; j > 0; j >>= 1) {
                for (int i = tid; i < m; i += 256) {
                    int ixj = i ^ j;
                    if (ixj > i) {
                        unsigned long long a = keys[i], b = keys[ixj];
                        bool desc = ((i & k) == 0);
                        if (desc ? (a < b) : (a > b)) { keys[i] = b; keys[ixj] = a; }
                    }
                }
                __syncthreads();
            }
        }
        sel = n < CAP ? n : CAP;
        if (tid < sel)
            toks[tid] = 0xFFFFFFFFu - (unsigned)(keys[tid] & 0xFFFFFFFFu);
    } else {
        // fallback (n > 2048): repeated block-wide argmax from global
        sel = CAP;
        unsigned long long prev = 0xFFFFFFFFFFFFFFFFULL;
        for (int r = 0; r < CAP; ++r) {
            unsigned long long best = 0ULL;
            for (int j = tid; j < n; j += 256) {
                unsigned long long kk = g_keys[(size_t)e * LISTCAP + j];
                if (kk < prev && kk > best) best = kk;
            }
            red[tid] = best;
            __syncthreads();
            for (int s2 = 128; s2; s2 >>= 1) {
                if (tid < s2 && red[tid + s2] > red[tid]) red[tid] = red[tid + s2];
                __syncthreads();
            }
            if (tid == 0)
                toks[r] = 0xFFFFFFFFu - (unsigned)(red[0] & 0xFFFFFFFFu);
            prev = red[0];
            __syncthreads();
        }
    }
    __syncthreads();
    if (tid < CAP && tid >= sel) toks[tid] = 0xFFFFFFFFu;
    __syncthreads();
    // ascending bitonic sort of selected token ids -> slot = rank (cumsum semantics)
    for (int k = 2; k <= CAP; k <<= 1) {
        for (int j = k >> 1; j > 0; j >>= 1) {
            if (tid < CAP) {
                int i = tid, ixj = i ^ j;
                if (ixj > i) {
                    unsigned a = toks[i], b = toks[ixj];
                    bool asc = ((i & k) == 0);
                    if (asc ? (a > b) : (a < b)) { toks[i] = b; toks[ixj] = a; }
                }
            }
            __syncthreads();
        }
    }
    if (tid < sel) g_slot[toks[tid]] = tid;
}

// ---------------- Kernel D: sparse scatter ----------------
__global__ void scatter_kernel(float* __restrict__ out) {
    const int t = blockIdx.x * blockDim.x + threadIdx.x;
    if (t >= S) return;
    const int s = g_slot[t];
    if (s >= 0) {
        const int e = g_expert[t];
        const size_t idx = (size_t)t * ROW + (size_t)e * CAP + s;
        out[OFF_COMBINE + idx] = g_gate[t];
        out[OFF_MASK + idx]    = 1.0f;
    }
}

// ---------------- Kernel E: l_aux + exp_counts ----------------
__global__ void scalars_kernel(float* __restrict__ out) {
    __shared__ float prod[E];
    const int e = threadIdx.x;
    if (e < E) {
        float cs = 0.f;
        for (int b = 0; b < S / 8; ++b) cs += g_colsum_part[b * E + e];
        out[OFF_COUNTS + e] = (float)g_cnt[e];
        prod[e] = cs * (float)g_cnt[e];
    }
    __syncthreads();
    if (e == 0) {
        float a = 0.f;
        for (int i = 0; i < E; ++i) a += prod[i];
        out[0] = a * ((float)E / ((float)S * (float)S));
    }
}

// ---------------- launch ----------------
extern "C" void kernel_launch(void* const* d_in, const int* in_sizes, int n_in,
                              void* d_out, int out_size) {
    const float *x = nullptr, *wg = nullptr, *noise = nullptr;
    for (int i = 0; i < n_in; ++i) {
        if (in_sizes[i] == S * DIM)      x     = (const float*)d_in[i];
        else if (in_sizes[i] == E * DIM) wg    = (const float*)d_in[i];
        else if (in_sizes[i] == S * E)   noise = (const float*)d_in[i];
    }
    float* out = (float*)d_out;

    fused_gemm_zero_kernel<<<GEMM_BLOCKS + ZERO_BLOCKS, 256>>>(x, wg, out);
    gate_kernel<<<S / 8, 256>>>(noise);
    select_kernel<<<E, 256>>>();
    scatter_kernel<<<(S + 255) / 256, 256>>>(out);
    scalars_kernel<<<1, 64>>>(out);
}

// round 4
// speedup vs baseline: 1.3313x; 1.0897x over previous
#include <cuda_runtime.h>
#include <cstdint>

// Problem constants
#define S     8192
#define E     64
#define DIM   4096
#define CAP   128
#define KSPLIT 2
#define KPER  (DIM / KSPLIT)      // 2048
#define BK    32                  // k per chunk
#define NCHUNK (KPER / BK)        // 64
#define BM    128
#define MTILES (S / BM)           // 64
#define GEMM_BLOCKS (MTILES * KSPLIT)  // 128
#define ZERO_BLOCKS 1792
#define LISTCAP 8192

// smem: double buffer, each buf = x tile 16KB + w tile 8KB
#define BUF_BYTES 24576
#define WOFF 16384
#define SMEM_BYTES (2 * BUF_BYTES)   // 48KB

// Output layout (float32):
#define OFF_COMBINE 1ULL
#define ROW (E * CAP)
#define OFF_MASK   (1ULL + (unsigned long long)S * ROW)
#define OFF_COUNTS (1ULL + 2ULL * (unsigned long long)S * ROW)

// ---------------- device scratch ----------------
__device__ float g_lpart[KSPLIT * S * E];
__device__ float g_colsum_part[(S / 8) * E];
__device__ int   g_expert[S];
__device__ float g_gate[S];
__device__ int   g_cnt[E];
__device__ unsigned long long g_keys[E * LISTCAP];

// ---------------- helpers ----------------
__device__ __forceinline__ void fma2(unsigned long long& acc,
                                     unsigned long long a,
                                     unsigned long long b) {
    asm("fma.rn.f32x2 %0, %1, %2, %3;" : "=l"(acc) : "l"(a), "l"(b), "l"(acc));
}
__device__ __forceinline__ uint32_t smem_u32(const void* p) {
    uint32_t a;
    asm("{ .reg .u64 t; cvta.to.shared.u64 t, %1; cvt.u32.u64 %0, t; }"
        : "=r"(a) : "l"(p));
    return a;
}
__device__ __forceinline__ void cp16(uint32_t dst, const void* src) {
    asm volatile("cp.async.ca.shared.global [%0], [%1], 16;"
                 :: "r"(dst), "l"(src) : "memory");
}

// prefetch one chunk (x: 128x32 fp32, w: 64x32 fp32) into buffer `buf`
__device__ __forceinline__ void prefetch_chunk(uint32_t sbase, int buf,
                                               const float* __restrict__ x,
                                               const float* __restrict__ w,
                                               int tok0, int kglob, int tid) {
    const uint32_t xb = sbase + buf * BUF_BYTES;
    const uint32_t wb = xb + WOFF;
#pragma unroll
    for (int p = 0; p < 4; ++p) {
        const int u = tid + p * 256;
        const int t = u >> 3, v = u & 7;
        cp16(xb + (uint32_t)((v * BM + t) * 16),
             &x[(size_t)(tok0 + t) * DIM + kglob + v * 4]);
    }
#pragma unroll
    for (int p = 0; p < 2; ++p) {
        const int u = tid + p * 256;
        const int e = u >> 3, v = u & 7;
        cp16(wb + (uint32_t)((v * E + e) * 16),
             &w[(size_t)e * DIM + kglob + v * 4]);
    }
    asm volatile("cp.async.commit_group;" ::: "memory");
}

// ---------------- Kernel A: fused FFMA2 GEMM (cp.async pipelined) + zero-fill ---
__global__ void __launch_bounds__(256, 1) fused_gemm_zero_kernel(
        const float* __restrict__ x, const float* __restrict__ w,
        float* __restrict__ out) {
    extern __shared__ char smem[];
    const int tid = threadIdx.x;

    if (blockIdx.x >= GEMM_BLOCKS) {
        // ---------- zero-fill branch (DRAM-bound) ----------
        const int zid = blockIdx.x - GEMM_BLOCKS;
        if (zid == 0 && tid < E) g_cnt[tid] = 0;
        const size_t nf4 = (OFF_COUNTS - 4ULL) >> 2;
        float4* p = reinterpret_cast<float4*>(out + 4);
        const size_t stride = (size_t)ZERO_BLOCKS * 256;
        const float4 z = make_float4(0.f, 0.f, 0.f, 0.f);
        for (size_t i = (size_t)zid * 256 + tid; i < nf4; i += stride) p[i] = z;
        if (zid == 0 && tid < 3) out[1 + tid] = 0.f;
        if (zid == 0 && tid == 0)
            for (size_t i = 4 + 4 * nf4; i < OFF_COUNTS; ++i) out[i] = 0.f;
        return;
    }

    // ---------- GEMM branch ----------
    const uint32_t sbase = smem_u32(smem);
    const int tx = tid & 15;          // expert lane: experts tx + 16j
    const int ty = tid >> 4;          // token lane:  tokens ty + 16i
    const int mt = blockIdx.x & (MTILES - 1);
    const int ks = blockIdx.x >> 6;   // MTILES == 64
    const int tok0 = mt * BM;
    const int kbase = ks * KPER;

    unsigned long long acc[8][4];
#pragma unroll
    for (int i = 0; i < 8; ++i)
#pragma unroll
        for (int j = 0; j < 4; ++j) acc[i][j] = 0ULL;

    prefetch_chunk(sbase, 0, x, w, tok0, kbase, tid);

    for (int c = 0; c < NCHUNK; ++c) {
        if (c + 1 < NCHUNK) {
            prefetch_chunk(sbase, (c + 1) & 1, x, w, tok0,
                           kbase + (c + 1) * BK, tid);
            asm volatile("cp.async.wait_group 1;" ::: "memory");
        } else {
            asm volatile("cp.async.wait_group 0;" ::: "memory");
        }
        __syncthreads();

        const char* xb = smem + (c & 1) * BUF_BYTES;
        const char* wb = xb + WOFF;
#pragma unroll
        for (int pg = 0; pg < 8; ++pg) {
            ulonglong2 xv[8], wv[4];
#pragma unroll
            for (int i = 0; i < 8; ++i)
                xv[i] = *reinterpret_cast<const ulonglong2*>(
                    xb + (pg * BM + ty + 16 * i) * 16);
#pragma unroll
            for (int j = 0; j < 4; ++j)
                wv[j] = *reinterpret_cast<const ulonglong2*>(
                    wb + (pg * E + tx + 16 * j) * 16);
#pragma unroll
            for (int i = 0; i < 8; ++i)
#pragma unroll
                for (int j = 0; j < 4; ++j) {
                    fma2(acc[i][j], xv[i].x, wv[j].x);
                    fma2(acc[i][j], xv[i].y, wv[j].y);
                }
        }
        __syncthreads();
    }

#pragma unroll
    for (int i = 0; i < 8; ++i) {
        const int t = tok0 + ty + 16 * i;
#pragma unroll
        for (int j = 0; j < 4; ++j) {
            const int e = tx + 16 * j;
            float2 f = *reinterpret_cast<float2*>(&acc[i][j]);
            g_lpart[((size_t)ks * S + t) * E + e] = f.x + f.y;
        }
    }
}

// ---------------- Kernel B: reduce split-K, softmax, argmax, key append --------
__global__ void __launch_bounds__(256) gate_kernel(const float* __restrict__ noise) {
    __shared__ float sg[8][E];
    const int tid = threadIdx.x;
    const int wp = tid >> 5;
    const int lane = tid & 31;
    const int t = blockIdx.x * 8 + wp;
    const int e0 = lane, e1 = lane + 32;

    float l0 = 0.f, l1 = 0.f;
#pragma unroll
    for (int ks = 0; ks < KSPLIT; ++ks) {
        l0 += g_lpart[((size_t)ks * S + t) * E + e0];
        l1 += g_lpart[((size_t)ks * S + t) * E + e1];
    }
    float m = fmaxf(l0, l1);
#pragma unroll
    for (int off = 16; off > 0; off >>= 1)
        m = fmaxf(m, __shfl_xor_sync(0xffffffffu, m, off));
    float p0 = expf(l0 - m), p1 = expf(l1 - m);
    float ssum = p0 + p1;
#pragma unroll
    for (int off = 16; off > 0; off >>= 1)
        ssum += __shfl_xor_sync(0xffffffffu, ssum, off);
    float g0 = p0 / ssum, g1 = p1 / ssum;

    // argmax, ties -> lowest index
    float bv; int bi;
    if (l0 >= l1) { bv = l0; bi = e0; } else { bv = l1; bi = e1; }
#pragma unroll
    for (int off = 16; off > 0; off >>= 1) {
        float ov = __shfl_xor_sync(0xffffffffu, bv, off);
        int   oi = __shfl_xor_sync(0xffffffffu, bi, off);
        if (ov > bv || (ov == bv && oi < bi)) { bv = ov; bi = oi; }
    }
    float gown = (bi < 32) ? g0 : g1;
    float gbest = __shfl_sync(0xffffffffu, gown, bi & 31);

    if (lane == 0) {
        g_expert[t] = bi;
        g_gate[t]   = gbest;
        const float nz = noise[(size_t)t * E + bi];
        const int pos = atomicAdd(&g_cnt[bi], 1);
        g_keys[(size_t)bi * LISTCAP + pos] =
            ((unsigned long long)__float_as_uint(nz) << 32)
            | (unsigned)(0xFFFFFFFFu - (unsigned)t);
    }

    sg[wp][e0] = g0;
    sg[wp][e1] = g1;
    __syncthreads();
    if (tid < E) {
        float cs = 0.f;
#pragma unroll
        for (int ww = 0; ww < 8; ++ww) cs += sg[ww][tid];
        g_colsum_part[blockIdx.x * E + tid] = cs;
    }
}

// ---------------- Kernel C: selection + slot ranks + fused scatter ----------
__global__ void __launch_bounds__(256) select_kernel(float* __restrict__ out) {
    const int e = blockIdx.x;
    const int tid = threadIdx.x;
    __shared__ unsigned long long keys[2048];
    __shared__ unsigned toks[CAP];
    __shared__ unsigned long long red[256];

    const int n = g_cnt[e];
    int sel;

    if (n <= 2048) {
        int m = 1;
        while (m < n) m <<= 1;
        for (int j = tid; j < m; j += 256)
            keys[j] = (j < n) ? g_keys[(size_t)e * LISTCAP + j] : 0ULL;
        __syncthreads();
        // descending bitonic sort on (noise, ~token) == jax top_k order
        for (int k = 2; k <= m; k <<= 1) {
            for (int j = k >> 1; j > 0; j >>= 1) {
                for (int i = tid; i < m; i += 256) {
                    int ixj = i ^ j;
                    if (ixj > i) {
                        unsigned long long a = keys[i], b = keys[ixj];
                        bool desc = ((i & k) == 0);
                        if (desc ? (a < b) : (a > b)) { keys[i] = b; keys[ixj] = a; }
                    }
                }
                __syncthreads();
            }
        }
        sel = n < CAP ? n : CAP;
        if (tid < sel)
            toks[tid] = 0xFFFFFFFFu - (unsigned)(keys[tid] & 0xFFFFFFFFu);
    } else {
        // fallback: repeated block-wide argmax from global
        sel = CAP;
        unsigned long long prev = 0xFFFFFFFFFFFFFFFFULL;
        for (int r = 0; r < CAP; ++r) {
            unsigned long long best = 0ULL;
            for (int j = tid; j < n; j += 256) {
                unsigned long long kk = g_keys[(size_t)e * LISTCAP + j];
                if (kk < prev && kk > best) best = kk;
            }
            red[tid] = best;
            __syncthreads();
            for (int s2 = 128; s2; s2 >>= 1) {
                if (tid < s2 && red[tid + s2] > red[tid]) red[tid] = red[tid + s2];
                __syncthreads();
            }
            if (tid == 0)
                toks[r] = 0xFFFFFFFFu - (unsigned)(red[0] & 0xFFFFFFFFu);
            prev = red[0];
            __syncthreads();
        }
    }
    __syncthreads();
    if (tid < CAP && tid >= sel) toks[tid] = 0xFFFFFFFFu;
    __syncthreads();
    // ascending sort of selected token ids -> slot = rank (cumsum semantics)
    for (int k = 2; k <= CAP; k <<= 1) {
        for (int j = k >> 1; j > 0; j >>= 1) {
            if (tid < CAP) {
                int i = tid, ixj = i ^ j;
                if (ixj > i) {
                    unsigned a = toks[i], b = toks[ixj];
                    bool asc = ((i & k) == 0);
                    if (asc ? (a > b) : (a < b)) { toks[i] = b; toks[ixj] = a; }
                }
            }
            __syncthreads();
        }
    }
    if (tid < sel) {
        const unsigned t = toks[tid];
        const size_t idx = (size_t)t * ROW + (size_t)e * CAP + tid;
        out[OFF_COMBINE + idx] = g_gate[t];
        out[OFF_MASK + idx]    = 1.0f;
    }
}

// ---------------- Kernel E: l_aux + exp_counts ----------------
__global__ void scalars_kernel(float* __restrict__ out) {
    __shared__ float prod[E];
    const int e = threadIdx.x;
    if (e < E) {
        float cs = 0.f;
        for (int b = 0; b < S / 8; ++b) cs += g_colsum_part[b * E + e];
        out[OFF_COUNTS + e] = (float)g_cnt[e];
        prod[e] = cs * (float)g_cnt[e];
    }
    __syncthreads();
    if (e == 0) {
        float a = 0.f;
        for (int i = 0; i < E; ++i) a += prod[i];
        out[0] = a * ((float)E / ((float)S * (float)S));
    }
}

// ---------------- launch ----------------
extern "C" void kernel_launch(void* const* d_in, const int* in_sizes, int n_in,
                              void* d_out, int out_size) {
    const float *x = nullptr, *wg = nullptr, *noise = nullptr;
    for (int i = 0; i < n_in; ++i) {
        if (in_sizes[i] == S * DIM)      x     = (const float*)d_in[i];
        else if (in_sizes[i] == E * DIM) wg    = (const float*)d_in[i];
        else if (in_sizes[i] == S * E)   noise = (const float*)d_in[i];
    }
    float* out = (float*)d_out;

    static bool attr_set = false;
    if (!attr_set) {
        cudaFuncSetAttribute(fused_gemm_zero_kernel,
                             cudaFuncAttributeMaxDynamicSharedMemorySize, SMEM_BYTES);
        attr_set = true;
    }

    fused_gemm_zero_kernel<<<GEMM_BLOCKS + ZERO_BLOCKS, 256, SMEM_BYTES>>>(x, wg, out);
    gate_kernel<<<S / 8, 256>>>(noise);
    select_kernel<<<E, 256>>>(out);
    scalars_kernel<<<1, 64>>>(out);
}